// round 5
// baseline (speedup 1.0000x reference)
#include <cuda_runtime.h>

// Vanilla tanh RNN: B=512, S=4096, H=40, fp32.
// out = concat( [B*S] per-step fc outputs , [B*H] final hidden )
//
// One warp per batch (128 CTAs x 4 warps ~ 1 warp/SMSP), chain-optimized:
//  - h broadcast via shared double buffer with NO syncwarp: shared ops from a
//    convergent warp complete in issue order (STS wavefront precedes the later
//    LDS wavefront in the in-order MIO pipe); asm volatile pins compiler order.
//  - all weights/biases pre-scaled by 2*log2(e) so the matvec directly yields
//    the EX2 argument: tanh(z) = 1 - 2*rcp(ex2(K*z)+1), no pre-scale FMUL.
//  - lanes 0-7 compute rows {l, 32+l}; lanes 8-31's second slot computes
//    K*(fc_w . h + fc_b); lane 8 stores it (un-scaled) one step behind.

#define BATCH 512
#define SEQ   4096
#define HID   40
#define KCH   64
#define WPB   4
#define THREADS (WPB * 32)
#define FULLM 0xffffffffu
#define KSC  2.8853900817779268f   // 2*log2(e)
#define KINV 0.3465735902799726f   // ln(2)/2

typedef unsigned long long u64;

__device__ __forceinline__ u64 pack2(float lo, float hi) {
    u64 r;
    asm("mov.b64 %0, {%1, %2};" : "=l"(r) : "f"(lo), "f"(hi));
    return r;
}
__device__ __forceinline__ void unpack2(u64 v, float& lo, float& hi) {
    asm("mov.b64 {%0, %1}, %2;" : "=f"(lo), "=f"(hi) : "l"(v));
}
__device__ __forceinline__ u64 fma2(u64 a, u64 b, u64 c) {
    u64 d;
    asm("fma.rn.f32x2 %0, %1, %2, %3;" : "=l"(d) : "l"(a), "l"(b), "l"(c));
    return d;
}
__device__ __forceinline__ u64 add2(u64 a, u64 b) {
    u64 d;
    asm("add.rn.f32x2 %0, %1, %2;" : "=l"(d) : "l"(a), "l"(b));
    return d;
}
__device__ __forceinline__ void lds2(u64& a, u64& b, unsigned off) {
    asm volatile("ld.shared.v2.u64 {%0, %1}, [%2];"
                 : "=l"(a), "=l"(b) : "r"(off) : "memory");
}
__device__ __forceinline__ void sts1(unsigned off, float v) {
    asm volatile("st.shared.f32 [%0], %1;" :: "r"(off), "f"(v) : "memory");
}

struct Lane {
    u64 wm[HID / 2], wx[HID / 2];
    float wih_m, cb_m, wih_x, cb_x;
};

// one recurrence step: read h from rd, write new h to wr; returns scaled fc z
__device__ __forceinline__ float rnn_step(
    unsigned rd, unsigned wr, float xv, int l,
    const Lane& W, float& hm, float& hxv)
{
    u64 hp[HID / 2];
#pragma unroll
    for (int q = 0; q < HID / 4; q++)
        lds2(hp[2 * q], hp[2 * q + 1], rd + 16u * q);

    u64 a0 = pack2(fmaf(xv, W.wih_m, W.cb_m), 0.0f);
    u64 c0 = pack2(fmaf(xv, W.wih_x, W.cb_x), 0.0f);
    u64 a1 = 0ull, a2 = 0ull, a3 = 0ull;
    u64 c1 = 0ull, c2 = 0ull, c3 = 0ull;
#pragma unroll
    for (int j = 0; j < HID / 2; j += 4) {
        a0 = fma2(W.wm[j + 0], hp[j + 0], a0);
        a1 = fma2(W.wm[j + 1], hp[j + 1], a1);
        a2 = fma2(W.wm[j + 2], hp[j + 2], a2);
        a3 = fma2(W.wm[j + 3], hp[j + 3], a3);
        c0 = fma2(W.wx[j + 0], hp[j + 0], c0);
        c1 = fma2(W.wx[j + 1], hp[j + 1], c1);
        c2 = fma2(W.wx[j + 2], hp[j + 2], c2);
        c3 = fma2(W.wx[j + 3], hp[j + 3], c3);
    }
    u64 am = add2(add2(a0, a1), add2(a2, a3));
    u64 cm = add2(add2(c0, c1), add2(c2, c3));
    float alo, ahi, clo, chi;
    unpack2(am, alo, ahi);
    unpack2(cm, clo, chi);
    float zm = alo + ahi;              // = 2*log2(e) * z_row
    float zc = clo + chi;              // lane>=8: 2*log2(e) * (fc.h + fc_b)

    float em, rm, ex_, rx_;
    asm("ex2.approx.f32 %0, %1;" : "=f"(em) : "f"(zm));
    asm("ex2.approx.f32 %0, %1;" : "=f"(ex_) : "f"(zc));
    asm("rcp.approx.f32 %0, %1;" : "=f"(rm) : "f"(em + 1.0f));
    asm("rcp.approx.f32 %0, %1;" : "=f"(rx_) : "f"(ex_ + 1.0f));
    hm  = fmaf(-2.0f, rm, 1.0f);
    hxv = fmaf(-2.0f, rx_, 1.0f);

    sts1(wr + 4u * l, hm);
    if (l < 8) sts1(wr + 4u * (32 + l), hxv);
    return zc;
}

__global__ void __launch_bounds__(THREADS, 1) rnn_kernel(
    const float* __restrict__ x,       // [B, S]
    const float* __restrict__ hidden,  // [B, H]
    const float* __restrict__ w_ih,    // [H]
    const float* __restrict__ w_hh,    // [H, H]
    const float* __restrict__ b_ih,    // [H]
    const float* __restrict__ b_hh,    // [H]
    const float* __restrict__ fc_w,    // [H]
    const float* __restrict__ fc_b,    // [1]
    float* __restrict__ out)           // [B*S] then [B*H]
{
    __shared__ __align__(16) float buf[WPB][2][HID];

    const int tid = threadIdx.x;
    const int wid = tid >> 5;
    const int l   = tid & 31;
    const int bg  = blockIdx.x * WPB + wid;

    Lane W;
#pragma unroll
    for (int j = 0; j < HID / 2; j++)
        W.wm[j] = pack2(w_hh[l * HID + 2 * j] * KSC,
                        w_hh[l * HID + 2 * j + 1] * KSC);

    const float* row2;
    if (l < 8) {
        row2 = &w_hh[(32 + l) * HID];
        W.wih_x = w_ih[32 + l] * KSC;
        W.cb_x  = (b_ih[32 + l] + b_hh[32 + l]) * KSC;
    } else {
        row2 = fc_w;
        W.wih_x = 0.0f;
        W.cb_x  = fc_b[0] * KSC;
    }
#pragma unroll
    for (int j = 0; j < HID / 2; j++)
        W.wx[j] = pack2(row2[2 * j] * KSC, row2[2 * j + 1] * KSC);

    W.wih_m = w_ih[l] * KSC;
    W.cb_m  = (b_ih[l] + b_hh[l]) * KSC;

    // initial state -> buf0
    float hm = hidden[bg * HID + l];
    float hxv = 0.0f;
    buf[wid][0][l] = hm;
    if (l < 8) {
        hxv = hidden[bg * HID + 32 + l];
        buf[wid][0][32 + l] = hxv;
    }
    __syncwarp();

    const unsigned off0 = (unsigned)__cvta_generic_to_shared(&buf[wid][0][0]);
    const unsigned off1 = (unsigned)__cvta_generic_to_shared(&buf[wid][1][0]);

    float xa = x[bg * SEQ + l];
    float xb = x[bg * SEQ + 32 + l];

    for (int chunk = 0; chunk < SEQ / KCH; chunk++) {
        const int t0  = chunk * KCH;
        const int t0n = (chunk + 1 < SEQ / KCH) ? t0 + KCH : 0;
        float xan = x[bg * SEQ + t0n + l];
        float xbn = x[bg * SEQ + t0n + 32 + l];

#pragma unroll 2
        for (int k = 0; k < KCH; k += 2) {
            // even step: read buf0, write buf1
            float xv0 = __shfl_sync(FULLM, (k & 32) ? xb : xa, k & 31);
            float zc0 = rnn_step(off0, off1, xv0, l, W, hm, hxv);
            if (l == 8) {
                int ti = t0 + k;
                out[bg * SEQ + (ti ? ti - 1 : 0)] = zc0 * KINV;
            }
            // odd step: read buf1, write buf0
            float xv1 = __shfl_sync(FULLM, ((k + 1) & 32) ? xb : xa, (k + 1) & 31);
            float zc1 = rnn_step(off1, off0, xv1, l, W, hm, hxv);
            if (l == 8) out[bg * SEQ + t0 + k] = zc1 * KINV;
        }

        xa = xan;
        xb = xbn;
    }

    // ---- epilogue: out[S-1] = fc . h_{S-1} + fc_b (h is in buf0, SEQ even) ----
    {
        u64 hp[HID / 2];
#pragma unroll
        for (int q = 0; q < HID / 4; q++)
            lds2(hp[2 * q], hp[2 * q + 1], off0 + 16u * q);
        u64 c0 = pack2(W.cb_x, 0.0f), c1 = 0ull, c2 = 0ull, c3 = 0ull;
#pragma unroll
        for (int j = 0; j < HID / 2; j += 4) {
            c0 = fma2(W.wx[j + 0], hp[j + 0], c0);
            c1 = fma2(W.wx[j + 1], hp[j + 1], c1);
            c2 = fma2(W.wx[j + 2], hp[j + 2], c2);
            c3 = fma2(W.wx[j + 3], hp[j + 3], c3);
        }
        u64 cm = add2(add2(c0, c1), add2(c2, c3));
        float clo, chi;
        unpack2(cm, clo, chi);
        if (l == 8) out[bg * SEQ + SEQ - 1] = (clo + chi) * KINV;
    }

    // ---- final hidden ----
    out[BATCH * SEQ + bg * HID + l] = hm;
    if (l < 8) out[BATCH * SEQ + bg * HID + 32 + l] = hxv;
}

extern "C" void kernel_launch(void* const* d_in, const int* in_sizes, int n_in,
                              void* d_out, int out_size) {
    const float* x      = (const float*)d_in[0];
    const float* hidden = (const float*)d_in[1];
    const float* w_ih   = (const float*)d_in[2];
    const float* w_hh   = (const float*)d_in[3];
    const float* b_ih   = (const float*)d_in[4];
    const float* b_hh   = (const float*)d_in[5];
    const float* fc_w   = (const float*)d_in[6];
    const float* fc_b   = (const float*)d_in[7];
    float* out = (float*)d_out;

    rnn_kernel<<<BATCH / WPB, THREADS>>>(x, hidden, w_ih, w_hh, b_ih, b_hh,
                                         fc_w, fc_b, out);
}

// round 6
// speedup vs baseline: 1.2652x; 1.2652x over previous
#include <cuda_runtime.h>

// Vanilla tanh RNN: B=512, S=4096, H=40, fp32.
// out = concat( [B*S] per-step fc outputs , [B*H] final hidden )
//
// TWO batches per warp, chains interleaved: 256 warps = 128 CTAs x 2 warps.
// Each warp carries batches {2wg, 2wg+1}; W_hh/fc weights live once in
// registers (shared by both batches), h broadcast via per-batch shared
// double buffers (STS + one syncwarp per step + broadcast LDS.v2.u64).
// Batch B's FMA stream fills batch A's LDS/MUFU stall bubbles.
// Weights pre-scaled by 2*log2(e): matvec directly yields the EX2 argument,
// tanh(z) = 1 - 2*rcp(ex2(Kz)+1). Lanes 0-7 second slot = rows 32..39;
// lanes 8-31 second slot = K*(fc_w.h + fc_b); lane 8 stores it (un-scaled,
// one step behind).

#define BATCH 512
#define SEQ   4096
#define HID   40
#define KCH   64
#define WPB   2
#define THREADS (WPB * 32)
#define FULLM 0xffffffffu
#define KSC  2.8853900817779268f   // 2*log2(e)
#define KINV 0.3465735902799726f   // ln(2)/2

typedef unsigned long long u64;

__device__ __forceinline__ u64 pack2(float lo, float hi) {
    u64 r;
    asm("mov.b64 %0, {%1, %2};" : "=l"(r) : "f"(lo), "f"(hi));
    return r;
}
__device__ __forceinline__ void unpack2(u64 v, float& lo, float& hi) {
    asm("mov.b64 {%0, %1}, %2;" : "=f"(lo), "=f"(hi) : "l"(v));
}
__device__ __forceinline__ u64 fma2(u64 a, u64 b, u64 c) {
    u64 d;
    asm("fma.rn.f32x2 %0, %1, %2, %3;" : "=l"(d) : "l"(a), "l"(b), "l"(c));
    return d;
}
__device__ __forceinline__ u64 add2(u64 a, u64 b) {
    u64 d;
    asm("add.rn.f32x2 %0, %1, %2;" : "=l"(d) : "l"(a), "l"(b));
    return d;
}
__device__ __forceinline__ void lds2(u64& a, u64& b, unsigned off) {
    asm volatile("ld.shared.v2.u64 {%0, %1}, [%2];"
                 : "=l"(a), "=l"(b) : "r"(off) : "memory");
}
__device__ __forceinline__ void sts1(unsigned off, float v) {
    asm volatile("st.shared.f32 [%0], %1;" :: "r"(off), "f"(v) : "memory");
}

struct Lane {
    u64 wm[HID / 2], wx[HID / 2];
    float wih_m, cb_m, wih_x, cb_x;
};

// One step for BOTH batches. Reads h from rdA/rdB, writes new h to wrA/wrB.
// zcA/zcB get the (scaled) fc dot for lanes >= 8.
__device__ __forceinline__ void step2(
    unsigned rdA, unsigned wrA, unsigned rdB, unsigned wrB,
    float xvA, float xvB, int l, const Lane& W,
    float& hmA, float& hxA, float& hmB, float& hxB,
    float& zcA, float& zcB)
{
    u64 hA[HID / 2], hB[HID / 2];
#pragma unroll
    for (int q = 0; q < HID / 4; q++)
        lds2(hA[2 * q], hA[2 * q + 1], rdA + 16u * q);
#pragma unroll
    for (int q = 0; q < HID / 4; q++)
        lds2(hB[2 * q], hB[2 * q + 1], rdB + 16u * q);

    u64 aA0 = pack2(fmaf(xvA, W.wih_m, W.cb_m), 0.0f), aA1 = 0ull;
    u64 cA0 = pack2(fmaf(xvA, W.wih_x, W.cb_x), 0.0f), cA1 = 0ull;
    u64 aB0 = pack2(fmaf(xvB, W.wih_m, W.cb_m), 0.0f), aB1 = 0ull;
    u64 cB0 = pack2(fmaf(xvB, W.wih_x, W.cb_x), 0.0f), cB1 = 0ull;
#pragma unroll
    for (int j = 0; j < HID / 2; j += 2) {
        aA0 = fma2(W.wm[j + 0], hA[j + 0], aA0);
        aA1 = fma2(W.wm[j + 1], hA[j + 1], aA1);
        cA0 = fma2(W.wx[j + 0], hA[j + 0], cA0);
        cA1 = fma2(W.wx[j + 1], hA[j + 1], cA1);
        aB0 = fma2(W.wm[j + 0], hB[j + 0], aB0);
        aB1 = fma2(W.wm[j + 1], hB[j + 1], aB1);
        cB0 = fma2(W.wx[j + 0], hB[j + 0], cB0);
        cB1 = fma2(W.wx[j + 1], hB[j + 1], cB1);
    }
    u64 amA = add2(aA0, aA1), cmA = add2(cA0, cA1);
    u64 amB = add2(aB0, aB1), cmB = add2(cB0, cB1);
    float lo0, hi0, lo1, hi1, lo2, hi2, lo3, hi3;
    unpack2(amA, lo0, hi0);
    unpack2(cmA, lo1, hi1);
    unpack2(amB, lo2, hi2);
    unpack2(cmB, lo3, hi3);
    float zmA = lo0 + hi0, zA = lo1 + hi1;
    float zmB = lo2 + hi2, zB = lo3 + hi3;
    zcA = zA;
    zcB = zB;

    float e0, e1, e2, e3, r0, r1, r2, r3;
    asm("ex2.approx.f32 %0, %1;" : "=f"(e0) : "f"(zmA));
    asm("ex2.approx.f32 %0, %1;" : "=f"(e1) : "f"(zA));
    asm("ex2.approx.f32 %0, %1;" : "=f"(e2) : "f"(zmB));
    asm("ex2.approx.f32 %0, %1;" : "=f"(e3) : "f"(zB));
    asm("rcp.approx.f32 %0, %1;" : "=f"(r0) : "f"(e0 + 1.0f));
    asm("rcp.approx.f32 %0, %1;" : "=f"(r1) : "f"(e1 + 1.0f));
    asm("rcp.approx.f32 %0, %1;" : "=f"(r2) : "f"(e2 + 1.0f));
    asm("rcp.approx.f32 %0, %1;" : "=f"(r3) : "f"(e3 + 1.0f));
    hmA = fmaf(-2.0f, r0, 1.0f);
    hxA = fmaf(-2.0f, r1, 1.0f);
    hmB = fmaf(-2.0f, r2, 1.0f);
    hxB = fmaf(-2.0f, r3, 1.0f);

    sts1(wrA + 4u * l, hmA);
    sts1(wrB + 4u * l, hmB);
    if (l < 8) {
        sts1(wrA + 4u * (32 + l), hxA);
        sts1(wrB + 4u * (32 + l), hxB);
    }
}

__global__ void __launch_bounds__(THREADS, 1) rnn_kernel(
    const float* __restrict__ x,       // [B, S]
    const float* __restrict__ hidden,  // [B, H]
    const float* __restrict__ w_ih,    // [H]
    const float* __restrict__ w_hh,    // [H, H]
    const float* __restrict__ b_ih,    // [H]
    const float* __restrict__ b_hh,    // [H]
    const float* __restrict__ fc_w,    // [H]
    const float* __restrict__ fc_b,    // [1]
    float* __restrict__ out)           // [B*S] then [B*H]
{
    __shared__ __align__(16) float buf[WPB][2][2][HID];  // [warp][batch][slot][h]

    const int tid = threadIdx.x;
    const int wid = tid >> 5;
    const int l   = tid & 31;
    const int wg  = blockIdx.x * WPB + wid;   // 0..255
    const int bA  = 2 * wg;
    const int bB  = 2 * wg + 1;

    Lane W;
#pragma unroll
    for (int j = 0; j < HID / 2; j++)
        W.wm[j] = pack2(w_hh[l * HID + 2 * j] * KSC,
                        w_hh[l * HID + 2 * j + 1] * KSC);

    const float* row2;
    if (l < 8) {
        row2 = &w_hh[(32 + l) * HID];
        W.wih_x = w_ih[32 + l] * KSC;
        W.cb_x  = (b_ih[32 + l] + b_hh[32 + l]) * KSC;
    } else {
        row2 = fc_w;
        W.wih_x = 0.0f;
        W.cb_x  = fc_b[0] * KSC;
    }
#pragma unroll
    for (int j = 0; j < HID / 2; j++)
        W.wx[j] = pack2(row2[2 * j] * KSC, row2[2 * j + 1] * KSC);

    W.wih_m = w_ih[l] * KSC;
    W.cb_m  = (b_ih[l] + b_hh[l]) * KSC;

    // ---- initial state -> slot 0 of each batch ----
    float hmA = hidden[bA * HID + l];
    float hmB = hidden[bB * HID + l];
    float hxA = 0.0f, hxB = 0.0f;
    buf[wid][0][0][l] = hmA;
    buf[wid][1][0][l] = hmB;
    if (l < 8) {
        hxA = hidden[bA * HID + 32 + l];
        hxB = hidden[bB * HID + 32 + l];
        buf[wid][0][0][32 + l] = hxA;
        buf[wid][1][0][32 + l] = hxB;
    }
    __syncwarp();

    const unsigned offA0 = (unsigned)__cvta_generic_to_shared(&buf[wid][0][0][0]);
    const unsigned offA1 = (unsigned)__cvta_generic_to_shared(&buf[wid][0][1][0]);
    const unsigned offB0 = (unsigned)__cvta_generic_to_shared(&buf[wid][1][0][0]);
    const unsigned offB1 = (unsigned)__cvta_generic_to_shared(&buf[wid][1][1][0]);

    float xaA = x[bA * SEQ + l],      xbA = x[bA * SEQ + 32 + l];
    float xaB = x[bB * SEQ + l],      xbB = x[bB * SEQ + 32 + l];

    for (int chunk = 0; chunk < SEQ / KCH; chunk++) {
        const int t0  = chunk * KCH;
        const int t0n = (chunk + 1 < SEQ / KCH) ? t0 + KCH : 0;
        float xanA = x[bA * SEQ + t0n + l], xbnA = x[bA * SEQ + t0n + 32 + l];
        float xanB = x[bB * SEQ + t0n + l], xbnB = x[bB * SEQ + t0n + 32 + l];

#pragma unroll 1
        for (int k = 0; k < KCH; k += 2) {
            float zcA, zcB;
            // even step: slot0 -> slot1
            float xvA0 = __shfl_sync(FULLM, (k & 32) ? xbA : xaA, k & 31);
            float xvB0 = __shfl_sync(FULLM, (k & 32) ? xbB : xaB, k & 31);
            __syncwarp();
            step2(offA0, offA1, offB0, offB1, xvA0, xvB0, l, W,
                  hmA, hxA, hmB, hxB, zcA, zcB);
            if (l == 8) {
                int ti = t0 + k;
                int tp = ti ? ti - 1 : 0;
                out[bA * SEQ + tp] = zcA * KINV;
                out[bB * SEQ + tp] = zcB * KINV;
            }
            // odd step: slot1 -> slot0
            int k1 = k + 1;
            float xvA1 = __shfl_sync(FULLM, (k1 & 32) ? xbA : xaA, k1 & 31);
            float xvB1 = __shfl_sync(FULLM, (k1 & 32) ? xbB : xaB, k1 & 31);
            __syncwarp();
            step2(offA1, offA0, offB1, offB0, xvA1, xvB1, l, W,
                  hmA, hxA, hmB, hxB, zcA, zcB);
            if (l == 8) {
                out[bA * SEQ + t0 + k] = zcA * KINV;
                out[bB * SEQ + t0 + k] = zcB * KINV;
            }
        }

        xaA = xanA; xbA = xbnA;
        xaB = xanB; xbB = xbnB;
    }

    // ---- epilogue: out[S-1] = fc . h_{S-1} + fc_b (h in slot 0, SEQ even) ----
    __syncwarp();
    {
        u64 hA[HID / 2], hB[HID / 2];
#pragma unroll
        for (int q = 0; q < HID / 4; q++) {
            lds2(hA[2 * q], hA[2 * q + 1], offA0 + 16u * q);
            lds2(hB[2 * q], hB[2 * q + 1], offB0 + 16u * q);
        }
        u64 cA0 = pack2(W.cb_x, 0.0f), cA1 = 0ull;
        u64 cB0 = pack2(W.cb_x, 0.0f), cB1 = 0ull;
#pragma unroll
        for (int j = 0; j < HID / 2; j += 2) {
            cA0 = fma2(W.wx[j + 0], hA[j + 0], cA0);
            cA1 = fma2(W.wx[j + 1], hA[j + 1], cA1);
            cB0 = fma2(W.wx[j + 0], hB[j + 0], cB0);
            cB1 = fma2(W.wx[j + 1], hB[j + 1], cB1);
        }
        u64 cmA = add2(cA0, cA1), cmB = add2(cB0, cB1);
        float lo0, hi0, lo1, hi1;
        unpack2(cmA, lo0, hi0);
        unpack2(cmB, lo1, hi1);
        if (l == 8) {
            out[bA * SEQ + SEQ - 1] = (lo0 + hi0) * KINV;
            out[bB * SEQ + SEQ - 1] = (lo1 + hi1) * KINV;
        }
    }

    // ---- final hidden ----
    out[BATCH * SEQ + bA * HID + l] = hmA;
    out[BATCH * SEQ + bB * HID + l] = hmB;
    if (l < 8) {
        out[BATCH * SEQ + bA * HID + 32 + l] = hxA;
        out[BATCH * SEQ + bB * HID + 32 + l] = hxB;
    }
}

extern "C" void kernel_launch(void* const* d_in, const int* in_sizes, int n_in,
                              void* d_out, int out_size) {
    const float* x      = (const float*)d_in[0];
    const float* hidden = (const float*)d_in[1];
    const float* w_ih   = (const float*)d_in[2];
    const float* w_hh   = (const float*)d_in[3];
    const float* b_ih   = (const float*)d_in[4];
    const float* b_hh   = (const float*)d_in[5];
    const float* fc_w   = (const float*)d_in[6];
    const float* fc_b   = (const float*)d_in[7];
    float* out = (float*)d_out;

    rnn_kernel<<<BATCH / (2 * WPB), THREADS>>>(x, hidden, w_ih, w_hh, b_ih, b_hh,
                                               fc_w, fc_b, out);
}

// round 7
// speedup vs baseline: 2.4043x; 1.9004x over previous
#include <cuda_runtime.h>

// Vanilla tanh RNN: B=512, S=4096, H=40, fp32.
// out = concat( [B*S] per-step fc outputs , [B*H] final hidden )
//
// R3 structure (best: 561us): one warp per batch, 128 CTAs x 4 warps,
// h broadcast via shared double buffer (STS + syncwarp + broadcast LDS.v2.u64),
// matvec in packed fma.rn.f32x2, lanes 0-7 second slot = rows 32..39,
// lanes 8-31 second slot = fc_w.h + fc_b (lane 8 stores it, one step behind).
// R7 change: tanh via single MUFU tanh.approx.f32 (chain 44 -> 16 cy),
// no weight pre-scaling needed.

#define BATCH 512
#define SEQ   4096
#define HID   40
#define KCH   64
#define WPB   4
#define THREADS (WPB * 32)
#define FULLM 0xffffffffu

typedef unsigned long long u64;

__device__ __forceinline__ u64 pack2(float lo, float hi) {
    u64 r;
    asm("mov.b64 %0, {%1, %2};" : "=l"(r) : "f"(lo), "f"(hi));
    return r;
}
__device__ __forceinline__ void unpack2(u64 v, float& lo, float& hi) {
    asm("mov.b64 {%0, %1}, %2;" : "=f"(lo), "=f"(hi) : "l"(v));
}
__device__ __forceinline__ u64 fma2(u64 a, u64 b, u64 c) {
    u64 d;
    asm("fma.rn.f32x2 %0, %1, %2, %3;" : "=l"(d) : "l"(a), "l"(b), "l"(c));
    return d;
}
__device__ __forceinline__ u64 add2(u64 a, u64 b) {
    u64 d;
    asm("add.rn.f32x2 %0, %1, %2;" : "=l"(d) : "l"(a), "l"(b));
    return d;
}
__device__ __forceinline__ void lds2(u64& a, u64& b, unsigned off) {
    asm volatile("ld.shared.v2.u64 {%0, %1}, [%2];"
                 : "=l"(a), "=l"(b) : "r"(off) : "memory");
}
__device__ __forceinline__ void sts1(unsigned off, float v) {
    asm volatile("st.shared.f32 [%0], %1;" :: "r"(off), "f"(v) : "memory");
}
__device__ __forceinline__ float tanh_mufu(float z) {
    float r;
    asm("tanh.approx.f32 %0, %1;" : "=f"(r) : "f"(z));
    return r;
}

struct Lane {
    u64 wm[HID / 2], wx[HID / 2];
    float wih_m, cb_m, wih_x, cb_x;
};

// one recurrence step: read h from rd, write new h to wr; returns fc z (lane>=8)
__device__ __forceinline__ float rnn_step(
    unsigned rd, unsigned wr, float xv, int l,
    const Lane& W, float& hm, float& hxv)
{
    u64 hp[HID / 2];
#pragma unroll
    for (int q = 0; q < HID / 4; q++)
        lds2(hp[2 * q], hp[2 * q + 1], rd + 16u * q);

    u64 a0 = pack2(fmaf(xv, W.wih_m, W.cb_m), 0.0f);
    u64 c0 = pack2(fmaf(xv, W.wih_x, W.cb_x), 0.0f);
    u64 a1 = 0ull, a2 = 0ull, a3 = 0ull;
    u64 c1 = 0ull, c2 = 0ull, c3 = 0ull;
#pragma unroll
    for (int j = 0; j < HID / 2; j += 4) {
        a0 = fma2(W.wm[j + 0], hp[j + 0], a0);
        a1 = fma2(W.wm[j + 1], hp[j + 1], a1);
        a2 = fma2(W.wm[j + 2], hp[j + 2], a2);
        a3 = fma2(W.wm[j + 3], hp[j + 3], a3);
        c0 = fma2(W.wx[j + 0], hp[j + 0], c0);
        c1 = fma2(W.wx[j + 1], hp[j + 1], c1);
        c2 = fma2(W.wx[j + 2], hp[j + 2], c2);
        c3 = fma2(W.wx[j + 3], hp[j + 3], c3);
    }
    u64 am = add2(add2(a0, a1), add2(a2, a3));
    u64 cm = add2(add2(c0, c1), add2(c2, c3));
    float alo, ahi, clo, chi;
    unpack2(am, alo, ahi);
    unpack2(cm, clo, chi);
    float zm = alo + ahi;
    float zc = clo + chi;              // lane>=8: fc_w . h_{t-1} + fc_b

    hm  = tanh_mufu(zm);
    hxv = tanh_mufu(zc);

    sts1(wr + 4u * l, hm);
    if (l < 8) sts1(wr + 4u * (32 + l), hxv);
    return zc;
}

__global__ void __launch_bounds__(THREADS, 1) rnn_kernel(
    const float* __restrict__ x,       // [B, S]
    const float* __restrict__ hidden,  // [B, H]
    const float* __restrict__ w_ih,    // [H]
    const float* __restrict__ w_hh,    // [H, H]
    const float* __restrict__ b_ih,    // [H]
    const float* __restrict__ b_hh,    // [H]
    const float* __restrict__ fc_w,    // [H]
    const float* __restrict__ fc_b,    // [1]
    float* __restrict__ out)           // [B*S] then [B*H]
{
    __shared__ __align__(16) float buf[WPB][2][HID];

    const int tid = threadIdx.x;
    const int wid = tid >> 5;
    const int l   = tid & 31;
    const int bg  = blockIdx.x * WPB + wid;

    Lane W;
#pragma unroll
    for (int j = 0; j < HID / 2; j++)
        W.wm[j] = pack2(w_hh[l * HID + 2 * j], w_hh[l * HID + 2 * j + 1]);

    const float* row2;
    if (l < 8) {
        row2 = &w_hh[(32 + l) * HID];
        W.wih_x = w_ih[32 + l];
        W.cb_x  = b_ih[32 + l] + b_hh[32 + l];
    } else {
        row2 = fc_w;
        W.wih_x = 0.0f;
        W.cb_x  = fc_b[0];
    }
#pragma unroll
    for (int j = 0; j < HID / 2; j++)
        W.wx[j] = pack2(row2[2 * j], row2[2 * j + 1]);

    W.wih_m = w_ih[l];
    W.cb_m  = b_ih[l] + b_hh[l];

    // initial state -> buf0
    float hm = hidden[bg * HID + l];
    float hxv = 0.0f;
    buf[wid][0][l] = hm;
    if (l < 8) {
        hxv = hidden[bg * HID + 32 + l];
        buf[wid][0][32 + l] = hxv;
    }
    __syncwarp();

    const unsigned off0 = (unsigned)__cvta_generic_to_shared(&buf[wid][0][0]);
    const unsigned off1 = (unsigned)__cvta_generic_to_shared(&buf[wid][1][0]);

    float xa = x[bg * SEQ + l];
    float xb = x[bg * SEQ + 32 + l];

    for (int chunk = 0; chunk < SEQ / KCH; chunk++) {
        const int t0  = chunk * KCH;
        const int t0n = (chunk + 1 < SEQ / KCH) ? t0 + KCH : 0;
        float xan = x[bg * SEQ + t0n + l];
        float xbn = x[bg * SEQ + t0n + 32 + l];

#pragma unroll 2
        for (int k = 0; k < KCH; k += 2) {
            // even step: read buf0, write buf1
            float xv0 = __shfl_sync(FULLM, (k & 32) ? xb : xa, k & 31);
            __syncwarp();
            float zc0 = rnn_step(off0, off1, xv0, l, W, hm, hxv);
            if (l == 8) {
                int ti = t0 + k;
                out[bg * SEQ + (ti ? ti - 1 : 0)] = zc0;
            }
            // odd step: read buf1, write buf0
            float xv1 = __shfl_sync(FULLM, ((k + 1) & 32) ? xb : xa, (k + 1) & 31);
            __syncwarp();
            float zc1 = rnn_step(off1, off0, xv1, l, W, hm, hxv);
            if (l == 8) out[bg * SEQ + t0 + k] = zc1;
        }

        xa = xan;
        xb = xbn;
    }

    // ---- epilogue: out[S-1] = fc . h_{S-1} + fc_b (h is in buf0, SEQ even) ----
    __syncwarp();
    {
        u64 hp[HID / 2];
#pragma unroll
        for (int q = 0; q < HID / 4; q++)
            lds2(hp[2 * q], hp[2 * q + 1], off0 + 16u * q);
        u64 c0 = pack2(W.cb_x, 0.0f), c1 = 0ull, c2 = 0ull, c3 = 0ull;
#pragma unroll
        for (int j = 0; j < HID / 2; j += 4) {
            c0 = fma2(W.wx[j + 0], hp[j + 0], c0);
            c1 = fma2(W.wx[j + 1], hp[j + 1], c1);
            c2 = fma2(W.wx[j + 2], hp[j + 2], c2);
            c3 = fma2(W.wx[j + 3], hp[j + 3], c3);
        }
        u64 cm = add2(add2(c0, c1), add2(c2, c3));
        float clo, chi;
        unpack2(cm, clo, chi);
        if (l == 8) out[bg * SEQ + SEQ - 1] = clo + chi;
    }

    // ---- final hidden ----
    out[BATCH * SEQ + bg * HID + l] = hm;
    if (l < 8) out[BATCH * SEQ + bg * HID + 32 + l] = hxv;
}

extern "C" void kernel_launch(void* const* d_in, const int* in_sizes, int n_in,
                              void* d_out, int out_size) {
    const float* x      = (const float*)d_in[0];
    const float* hidden = (const float*)d_in[1];
    const float* w_ih   = (const float*)d_in[2];
    const float* w_hh   = (const float*)d_in[3];
    const float* b_ih   = (const float*)d_in[4];
    const float* b_hh   = (const float*)d_in[5];
    const float* fc_w   = (const float*)d_in[6];
    const float* fc_b   = (const float*)d_in[7];
    float* out = (float*)d_out;

    rnn_kernel<<<BATCH / WPB, THREADS>>>(x, hidden, w_ih, w_hh, b_ih, b_hh,
                                         fc_w, fc_b, out);
}